// round 8
// baseline (speedup 1.0000x reference)
#include <cuda_runtime.h>
#include <cuda_bf16.h>
#include <cstdint>

// Problem constants
#define NBM   64      // B*M = 2*32
#define LSEQ  512
#define CDIM  512
#define NH    8
#define HD    64
#define NROWS (NBM*LSEQ)   // 32768

// Scratch (all tf32-rounded; mma k-dims perm16'd within 16-groups):
//  g_xt: X rows, k perm16                [32768][512]
//  g_q,g_k: [bm][h][l][d'']  (d perm16)
//  g_v:     [bm][h][d][l'']  (l perm16)
//  g_wt:    [3][n][k'']      (k perm16)
__device__ float g_xt[NROWS*CDIM];
__device__ float g_q[NBM*NH*LSEQ*HD];
__device__ float g_k[NBM*NH*LSEQ*HD];
__device__ float g_v[NBM*NH*HD*LSEQ];
__device__ float g_wt[3*CDIM*CDIM];

// perm16: within a 16-group, logical index v (ks-half = v>>3, col = v&7)
// goes to position 4*(v&3) + ((v>>2)&1) + 2*((v>>3)&1).
// Thread t's LDS.128 at offset 4t then yields {ksA:t, ksA:t+4, ksB:t, ksB:t+4}.
__device__ __forceinline__ int p16(int v) {
    return 4 * (v & 3) + ((v >> 2) & 1) + 2 * ((v >> 3) & 1);
}

__device__ __forceinline__ unsigned f2tf(float f) {
    unsigned u;
    asm("cvt.rna.tf32.f32 %0, %1;" : "=r"(u) : "f"(f));
    return u;
}
__device__ __forceinline__ float f2tff(float f) { return __uint_as_float(f2tf(f)); }

__device__ __forceinline__ void mma_tf32(float* c, const unsigned* a, const unsigned* b) {
    asm("mma.sync.aligned.m16n8k8.row.col.f32.tf32.tf32.f32 "
        "{%0,%1,%2,%3}, {%4,%5,%6,%7}, {%8,%9}, {%0,%1,%2,%3};"
        : "+f"(c[0]), "+f"(c[1]), "+f"(c[2]), "+f"(c[3])
        : "r"(a[0]), "r"(a[1]), "r"(a[2]), "r"(a[3]),
          "r"(b[0]), "r"(b[1]));
}

__device__ __forceinline__ uint32_t smem_u32(const void* p) {
    uint32_t a;
    asm("{ .reg .u64 t; cvta.to.shared.u64 t, %1; cvt.u32.u64 %0, t; }" : "=r"(a) : "l"(p));
    return a;
}

#define CP16(dst, src) \
    asm volatile("cp.async.cg.shared.global [%0], [%1], 16;" :: "r"(dst), "l"(src) : "memory")
#define CP_COMMIT() asm volatile("cp.async.commit_group;" ::: "memory")
#define CP_WAIT(n)  asm volatile("cp.async.wait_group %0;" :: "n"(n) : "memory")

// ---------------------------------------------------------------------------
// Pre-pass A: g_xt = rna_tf32(x), k perm16'd.
// A float4 at fbase lands at positions (fbase>>2)&3 + 4*j within its 16-group.
// ---------------------------------------------------------------------------
__global__ __launch_bounds__(256) void xt_kernel(const float* __restrict__ x)
{
    int idx = blockIdx.x * 256 + threadIdx.x;          // float4 index
    float4 v = ((const float4*)x)[idx];
    int fbase = idx * 4;
    int grp   = fbase & ~15;
    int start = (fbase >> 2) & 3;
    float* dst = g_xt + grp + start;
    dst[0]  = f2tff(v.x);
    dst[4]  = f2tff(v.y);
    dst[8]  = f2tff(v.z);
    dst[12] = f2tff(v.w);
}

// ---------------------------------------------------------------------------
// Pre-pass B: Wt[mat][n][k''] = rna_tf32(W[k][n]), k perm16'd.
// ---------------------------------------------------------------------------
__global__ __launch_bounds__(256) void wt_kernel(
    const float* __restrict__ Wq, const float* __restrict__ Wk,
    const float* __restrict__ Wv)
{
    __shared__ float s[32][33];
    const float* W = (blockIdx.z == 0) ? Wq : (blockIdx.z == 1) ? Wk : Wv;
    const int k0 = blockIdx.x * 32, n0 = blockIdx.y * 32;
    const int tid = threadIdx.x;
    {
        int kl = tid >> 3, n4 = tid & 7;
        float4 v = *(const float4*)&W[(size_t)(k0 + kl) * CDIM + n0 + n4 * 4];
        s[kl][n4 * 4 + 0] = f2tff(v.x);
        s[kl][n4 * 4 + 1] = f2tff(v.y);
        s[kl][n4 * 4 + 2] = f2tff(v.z);
        s[kl][n4 * 4 + 3] = f2tff(v.w);
    }
    __syncthreads();
    {
        int nl = tid >> 3, k4 = tid & 7;
        float* rowp = g_wt + ((size_t)(blockIdx.z * CDIM + n0 + nl)) * CDIM;
        #pragma unroll
        for (int j = 0; j < 4; j++) {
            int kk = k0 + k4 * 4 + j;
            int kp = (kk & ~15) | p16(kk & 15);
            rowp[kp] = s[k4 * 4 + j][nl];
        }
    }
}

// ---------------------------------------------------------------------------
// Kernel 1: QKV projection, 2 output tiles per CTA (shared A staging).
// CTA: A tile 128 rows x 32k (double buffered) + two B tiles 128n x 32k.
// 8 warps as 2m x 4n, warp tile 64x32 per B tile. All frags LDS.128 (perm16).
// Grid x: 0..3 = (Q col t, K col t) pairs; 4..5 = (V col 2t, V col 2t+1).
// ---------------------------------------------------------------------------
#define QKV_AST   48                    // floats per 32-wide row (48%32==16)
#define QKV_TILE  (128*QKV_AST)         // 6144 floats per tile
#define QKV_BUF   (3*QKV_TILE)          // A + B0 + B1 = 18432 floats
#define QKV_SMEMB (2*QKV_BUF*4)         // 147456 bytes

__global__ __launch_bounds__(256, 1) void qkv_v4(
    const float* __restrict__ bq, const float* __restrict__ bk,
    const float* __restrict__ bv)
{
    extern __shared__ float smem[];
    const uint32_t sbase = smem_u32(smem);

    const int tid  = threadIdx.x;
    const int lane = tid & 31;
    const int warp = tid >> 5;
    const int g    = lane >> 2;
    const int t    = lane & 3;
    const int wm   = (warp >> 2) * 64;   // warp row offset (0/64)
    const int wn   = (warp & 3) * 32;    // warp col offset (0/32/64/96)

    const int gx = blockIdx.x;           // 0..5
    const int r0 = blockIdx.y * 128;

    int mat0, mat1, col0a, col0b;
    if (gx < 4) { mat0 = 0; mat1 = 1; col0a = gx * 128; col0b = gx * 128; }
    else        { mat0 = 2; mat1 = 2; col0a = (gx - 4) * 256; col0b = col0a + 128; }
    const float* bias0 = (mat0 == 0) ? bq : (mat0 == 1) ? bk : bv;
    const float* bias1 = (mat1 == 0) ? bq : (mat1 == 1) ? bk : bv;

    // Staging pointers: 12 cp.async of 16B per thread per stage
    const int srow = tid >> 3;           // 0..31 (+ i*32)
    const int sc4  = tid & 7;
    const float* xsrc  = g_xt + (size_t)(r0 + srow) * CDIM + sc4 * 4;
    const float* wsrc0 = g_wt + (size_t)(mat0 * CDIM + col0a + srow) * CDIM + sc4 * 4;
    const float* wsrc1 = g_wt + (size_t)(mat1 * CDIM + col0b + srow) * CDIM + sc4 * 4;
    const uint32_t sOff = (uint32_t)(srow * QKV_AST + sc4 * 4) * 4;

    auto stage = [&](int kt, int b) {
        const uint32_t aB = sbase + (uint32_t)b * (QKV_BUF * 4) + sOff;
        const float* xs = xsrc  + kt * 32;
        const float* w0 = wsrc0 + kt * 32;
        const float* w1 = wsrc1 + kt * 32;
        #pragma unroll
        for (int i = 0; i < 4; i++) {
            CP16(aB + i * (32 * QKV_AST * 4),                    xs + (size_t)i * 32 * CDIM);
            CP16(aB + QKV_TILE * 4 + i * (32 * QKV_AST * 4),     w0 + (size_t)i * 32 * CDIM);
            CP16(aB + 2 * QKV_TILE * 4 + i * (32 * QKV_AST * 4), w1 + (size_t)i * 32 * CDIM);
        }
        CP_COMMIT();
    };

    float acc[2][4][4][4];
    #pragma unroll
    for (int T = 0; T < 2; T++)
        #pragma unroll
        for (int mi = 0; mi < 4; mi++)
            #pragma unroll
            for (int ni = 0; ni < 4; ni++)
                #pragma unroll
                for (int e = 0; e < 4; e++) acc[T][mi][ni][e] = 0.f;

    stage(0, 0);

    for (int kt = 0; kt < 16; kt++) {
        const int b = kt & 1;
        if (kt + 1 < 16) { stage(kt + 1, b ^ 1); CP_WAIT(1); }
        else             { CP_WAIT(0); }
        __syncthreads();

        const unsigned* As = (const unsigned*)(smem + b * QKV_BUF);

        #pragma unroll
        for (int ksp = 0; ksp < 2; ksp++) {
            const int kc = ksp * 16 + 4 * t;
            unsigned aA[4][4], aB2[4][4];
            #pragma unroll
            for (int mi = 0; mi < 4; mi++) {
                int rb = wm + mi * 16 + g;
                uint4 lo = *(const uint4*)&As[rb * QKV_AST + kc];
                uint4 hi = *(const uint4*)&As[(rb + 8) * QKV_AST + kc];
                aA[mi][0] = lo.x; aA[mi][1] = hi.x; aA[mi][2] = lo.y; aA[mi][3] = hi.y;
                aB2[mi][0] = lo.z; aB2[mi][1] = hi.z; aB2[mi][2] = lo.w; aB2[mi][3] = hi.w;
            }
            #pragma unroll
            for (int T = 0; T < 2; T++) {
                const unsigned* Bs = As + (1 + T) * QKV_TILE;
                #pragma unroll
                for (int ni = 0; ni < 4; ni++) {
                    int nr = wn + ni * 8 + g;
                    uint4 u = *(const uint4*)&Bs[nr * QKV_AST + kc];
                    unsigned bA[2] = { u.x, u.y }, bB[2] = { u.z, u.w };
                    #pragma unroll
                    for (int mi = 0; mi < 4; mi++) {
                        mma_tf32(acc[T][mi][ni], aA[mi],  bA);
                        mma_tf32(acc[T][mi][ni], aB2[mi], bB);
                    }
                }
            }
        }
        __syncthreads();
    }

    // Epilogue: bias + tf32 round + perm16 scatter, per tile
    #pragma unroll
    for (int T = 0; T < 2; T++) {
        const int mat  = T ? mat1 : mat0;
        const int col0 = T ? col0b : col0a;
        const float* bias = T ? bias1 : bias0;
        float* qk = (mat == 0) ? g_q : g_k;

        #pragma unroll
        for (int mi = 0; mi < 4; mi++) {
            #pragma unroll
            for (int ep = 0; ep < 2; ep++) {
                int row = wm + mi * 16 + g + ep * 8;
                int R = r0 + row;
                int bm = R >> 9, l = R & 511;
                int lp = (l & ~15) | p16(l & 15);
                #pragma unroll
                for (int ni = 0; ni < 4; ni++) {
                    int c = col0 + wn + ni * 8 + t * 2;
                    int h = c >> 6, d = c & 63;
                    float v0 = f2tff(acc[T][mi][ni][2 * ep]     + bias[c]);
                    float v1 = f2tff(acc[T][mi][ni][2 * ep + 1] + bias[c + 1]);
                    if (mat < 2) {
                        float* base = qk + (((size_t)(bm * NH + h)) * LSEQ + l) * HD;
                        base[(d & ~15) | p16(d & 15)]             = v0;
                        base[((d + 1) & ~15) | p16((d + 1) & 15)] = v1;
                    } else {
                        size_t base = ((size_t)(bm * NH + h)) * HD;
                        g_v[(base + d)     * LSEQ + lp] = v0;
                        g_v[(base + d + 1) * LSEQ + lp] = v1;
                    }
                }
            }
        }
    }
}

// ---------------------------------------------------------------------------
// Kernel 2: flash attention per (bm, h, q-tile of 128 rows). 256 threads.
// O^T = V^T P^T: A = V^T (smem), B = P built in-register from sacc via
// shuffles -> NO P smem round-trip. All smem frags are LDS.128 (perm16).
// smem: Ks[2][128][80] | Vs[2][64][144] | Qs[128][80]
// ---------------------------------------------------------------------------
#define KST 80
#define VST 144
#define KS_OFF(b) ((b) * 128 * KST)
#define VS_OFF(b) (2 * 128 * KST + (b) * 64 * VST)
#define QS_OFF    (2 * 128 * KST + 2 * 64 * VST)
#define ATTN_FLOATS (QS_OFF + 128 * KST)
#define ATTN_SMEMB  (ATTN_FLOATS * 4)               // 196608 bytes

__global__ __launch_bounds__(256, 1) void attn_kernel(float* __restrict__ out)
{
    extern __shared__ float asmem[];
    const uint32_t sbase = smem_u32(asmem);

    const int qt = blockIdx.x;
    const int h  = blockIdx.y;
    const int bm = blockIdx.z;
    const int l0 = qt * 128;

    const int tid  = threadIdx.x;
    const int lane = tid & 31;
    const int warp = tid >> 5;
    const int g    = lane >> 2;
    const int t    = lane & 3;
    const int wr   = warp * 16;

    const float* qb = g_q + ((size_t)(bm * NH + h)) * LSEQ * HD;
    const float* kb = g_k + ((size_t)(bm * NH + h)) * LSEQ * HD;
    const float* vb = g_v + ((size_t)(bm * NH + h)) * HD * LSEQ;

    // ---- stage Q + K0 + V0 ----
    #pragma unroll
    for (int i = 0; i < 8; i++) {
        int idx = tid + i * 256;                    // 2048 chunks of 16B
        int row = idx >> 4, c16 = idx & 15;
        uint32_t dst = sbase + (uint32_t)(QS_OFF + row * KST + c16 * 4) * 4;
        CP16(dst, qb + (size_t)(l0 + row) * HD + c16 * 4);
    }
    #pragma unroll
    for (int i = 0; i < 8; i++) {
        int idx = tid + i * 256;
        int row = idx >> 4, c16 = idx & 15;
        uint32_t dst = sbase + (uint32_t)(KS_OFF(0) + row * KST + c16 * 4) * 4;
        CP16(dst, kb + (size_t)row * HD + c16 * 4);
    }
    #pragma unroll
    for (int i = 0; i < 8; i++) {
        int idx = tid + i * 256;
        int row = idx >> 5, c32 = idx & 31;
        uint32_t dst = sbase + (uint32_t)(VS_OFF(0) + row * VST + c32 * 4) * 4;
        CP16(dst, vb + (size_t)row * LSEQ + c32 * 4);
    }
    CP_COMMIT();
    CP_WAIT(0);
    __syncthreads();

    // Q fragments, register-resident (LDS.128, perm16)
    unsigned qa[8][4];
    {
        const unsigned* Qs = (const unsigned*)(asmem + QS_OFF);
        #pragma unroll
        for (int ksp = 0; ksp < 4; ksp++) {
            uint4 lo = *(const uint4*)&Qs[(wr + g) * KST + ksp * 16 + 4 * t];
            uint4 hi = *(const uint4*)&Qs[(wr + g + 8) * KST + ksp * 16 + 4 * t];
            qa[2*ksp][0]   = lo.x; qa[2*ksp][1]   = hi.x; qa[2*ksp][2]   = lo.y; qa[2*ksp][3]   = hi.y;
            qa[2*ksp+1][0] = lo.z; qa[2*ksp+1][1] = hi.z; qa[2*ksp+1][2] = lo.w; qa[2*ksp+1][3] = hi.w;
        }
    }

    // O^T accumulators: oacc[mi][nb]: c0=(q=wr+8nb+2t, d=16mi+g), c1=(q+1,d),
    // c2=(q, d+8), c3=(q+1, d+8)
    float oacc[4][2][4];
    #pragma unroll
    for (int mi = 0; mi < 4; mi++)
        #pragma unroll
        for (int nb = 0; nb < 2; nb++)
            #pragma unroll
            for (int e = 0; e < 4; e++) oacc[mi][nb][e] = 0.f;

    float mrow[2] = { -3.0e38f, -3.0e38f };
    float lsum[2] = { 0.f, 0.f };
    const float kInv = 1.4426950408889634f * 0.125f;  // log2(e)/sqrt(64)
    const int src0 = (lane & ~3) | (t >> 1);          // B-frag shuffle sources
    const int src1 = src0 + 2;

    for (int j = 0; j < 4; j++) {
        const int b = j & 1;
        if (j < 3) {   // prefetch next K/V (buffer b^1 free since iteration j-1)
            const int jn = (j + 1) * 128;
            #pragma unroll
            for (int i = 0; i < 8; i++) {
                int idx = tid + i * 256;
                int row = idx >> 4, c16 = idx & 15;
                uint32_t dst = sbase + (uint32_t)(KS_OFF(b ^ 1) + row * KST + c16 * 4) * 4;
                CP16(dst, kb + (size_t)(jn + row) * HD + c16 * 4);
            }
            #pragma unroll
            for (int i = 0; i < 8; i++) {
                int idx = tid + i * 256;
                int row = idx >> 5, c32 = idx & 31;
                uint32_t dst = sbase + (uint32_t)(VS_OFF(b ^ 1) + row * VST + c32 * 4) * 4;
                CP16(dst, vb + (size_t)row * LSEQ + jn + c32 * 4);
            }
            CP_COMMIT();
        }

        const unsigned* Ks = (const unsigned*)(asmem + KS_OFF(b));
        const unsigned* Vs = (const unsigned*)(asmem + VS_OFF(b));

        // ---- S = Q K^T : sacc[ni][e], rows (wr+g, wr+g+8), keys 8ni+2t(+1)
        float sacc[16][4];
        #pragma unroll
        for (int ni = 0; ni < 16; ni++)
            #pragma unroll
            for (int e = 0; e < 4; e++) sacc[ni][e] = 0.f;

        #pragma unroll
        for (int ksp = 0; ksp < 4; ksp++) {
            const int kc = ksp * 16 + 4 * t;
            #pragma unroll
            for (int ni = 0; ni < 16; ni++) {
                uint4 u = *(const uint4*)&Ks[(ni * 8 + g) * KST + kc];
                unsigned bA[2] = { u.x, u.y }, bB[2] = { u.z, u.w };
                mma_tf32(sacc[ni], qa[2*ksp],   bA);
                mma_tf32(sacc[ni], qa[2*ksp+1], bB);
            }
        }

        #pragma unroll
        for (int ni = 0; ni < 16; ni++)
            #pragma unroll
            for (int e = 0; e < 4; e++) sacc[ni][e] *= kInv;

        // ---- online softmax (base 2); sacc overwritten with rounded exp ----
        float alpha[2];
        #pragma unroll
        for (int rh = 0; rh < 2; rh++) {
            float mt = -3.0e38f;
            #pragma unroll
            for (int ni = 0; ni < 16; ni++) {
                mt = fmaxf(mt, sacc[ni][2 * rh]);
                mt = fmaxf(mt, sacc[ni][2 * rh + 1]);
            }
            mt = fmaxf(mt, __shfl_xor_sync(0xffffffffu, mt, 1));
            mt = fmaxf(mt, __shfl_xor_sync(0xffffffffu, mt, 2));
            float mnew = fmaxf(mrow[rh], mt);
            alpha[rh]  = exp2f(mrow[rh] - mnew);
            mrow[rh]   = mnew;
            float rs = 0.f;
            #pragma unroll
            for (int ni = 0; ni < 16; ni++) {
                float p0 = exp2f(sacc[ni][2 * rh]     - mnew);
                float p1 = exp2f(sacc[ni][2 * rh + 1] - mnew);
                rs += p0 + p1;
                sacc[ni][2 * rh]     = f2tff(p0);
                sacc[ni][2 * rh + 1] = f2tff(p1);
            }
            rs += __shfl_xor_sync(0xffffffffu, rs, 1);
            rs += __shfl_xor_sync(0xffffffffu, rs, 2);
            lsum[rh] = lsum[rh] * alpha[rh] + rs;
        }

        // rescale O^T by the output-row alphas (rows 2t / 2t+1 of each nb half)
        {
            float a00 = __shfl_sync(0xffffffffu, alpha[0], 8 * t);      // row 2t,   nb=0
            float a01 = __shfl_sync(0xffffffffu, alpha[0], 8 * t + 4);  // row 2t+1, nb=0
            float a10 = __shfl_sync(0xffffffffu, alpha[1], 8 * t);      // row 2t,   nb=1
            float a11 = __shfl_sync(0xffffffffu, alpha[1], 8 * t + 4);  // row 2t+1, nb=1
            #pragma unroll
            for (int mi = 0; mi < 4; mi++) {
                oacc[mi][0][0] *= a00; oacc[mi][0][2] *= a00;
                oacc[mi][0][1] *= a01; oacc[mi][0][3] *= a01;
                oacc[mi][1][0] *= a10; oacc[mi][1][2] *= a10;
                oacc[mi][1][1] *= a11; oacc[mi][1][3] *= a11;
            }
        }

        // ---- O^T += V^T P^T : A from Vs (LDS.128), B from sacc via shuffle
        #pragma unroll
        for (int ksp = 0; ksp < 8; ksp++) {
            const int kc = ksp * 16 + 4 * t;
            unsigned aA[4][4], aB[4][4];
            #pragma unroll
            for (int mi = 0; mi < 4; mi++) {
                uint4 lo = *(const uint4*)&Vs[(mi * 16 + g) * VST + kc];
                uint4 hi = *(const uint4*)&Vs[(mi * 16 + g + 8) * VST + kc];
                aA[mi][0] = lo.x; aA[mi][1] = hi.x; aA[mi][2] = lo.y; aA[mi][3] = hi.y;
                aB[mi][0] = lo.z; aB[mi][1] = hi.z; aB[mi][2] = lo.w; aB[mi][3] = hi.w;
            }
            #pragma unroll
            for (int h2 = 0; h2 < 2; h2++) {
                const int ks = 2 * ksp + h2;
                #pragma unroll
                for (int nb = 0; nb < 2; nb++) {
                    float v00 = __shfl_sync(0xffffffffu, sacc[ks][2 * nb],     src0);
                    float v01 = __shfl_sync(0xffffffffu, sacc[ks][2 * nb + 1], src0);
                    float v10 = __shfl_sync(0xffffffffu, sacc[ks][2 * nb],     src1);
                    float v11 = __shfl_sync(0xffffffffu, sacc[ks][2 * nb + 1], src1);
                    unsigned bf[2];
                    bf[0] = __float_as_uint((t & 1) ? v01 : v00);
                    bf[1] = __float_as_uint((t & 1) ? v11 : v10);
                    #pragma unroll
                    for (int mi = 0; mi < 4; mi++)
                        mma_tf32(oacc[mi][nb], h2 ? aB[mi] : aA[mi], bf);
                }
            }
        }

        if (j < 3) { CP_WAIT(0); }
        __syncthreads();
    }

    // ---- epilogue: per-output-row 1/lsum via shuffle, transposed STG ----
    float ls00 = __shfl_sync(0xffffffffu, lsum[0], 8 * t);       // row 2t,   nb0
    float ls01 = __shfl_sync(0xffffffffu, lsum[0], 8 * t + 4);   // row 2t+1, nb0
    float ls10 = __shfl_sync(0xffffffffu, lsum[1], 8 * t);       // row 2t,   nb1
    float ls11 = __shfl_sync(0xffffffffu, lsum[1], 8 * t + 4);   // row 2t+1, nb1
    float inv[2][2] = { { 1.f / ls00, 1.f / ls01 }, { 1.f / ls10, 1.f / ls11 } };

    #pragma unroll
    for (int nb = 0; nb < 2; nb++) {
        int q0 = l0 + wr + 8 * nb + 2 * t;
        float* o0 = out + ((size_t)bm * LSEQ + q0) * CDIM + h * HD + g;
        float* o1 = o0 + CDIM;   // q0+1
        #pragma unroll
        for (int mi = 0; mi < 4; mi++) {
            o0[mi * 16]     = oacc[mi][nb][0] * inv[nb][0];
            o1[mi * 16]     = oacc[mi][nb][1] * inv[nb][1];
            o0[mi * 16 + 8] = oacc[mi][nb][2] * inv[nb][0];
            o1[mi * 16 + 8] = oacc[mi][nb][3] * inv[nb][1];
        }
    }
}

extern "C" void kernel_launch(void* const* d_in, const int* in_sizes, int n_in,
                              void* d_out, int out_size)
{
    const float* x  = (const float*)d_in[0];
    const float* Wq = (const float*)d_in[1];
    const float* bq = (const float*)d_in[2];
    const float* Wk = (const float*)d_in[3];
    const float* bk = (const float*)d_in[4];
    const float* Wv = (const float*)d_in[5];
    const float* bv = (const float*)d_in[6];
    float* out = (float*)d_out;

    xt_kernel<<<NROWS * CDIM / 4 / 256, 256>>>(x);
    wt_kernel<<<dim3(16, 16, 3), 256>>>(Wq, Wk, Wv);

    cudaFuncSetAttribute(qkv_v4,
                         cudaFuncAttributeMaxDynamicSharedMemorySize, QKV_SMEMB);
    qkv_v4<<<dim3(6, 256), 256, QKV_SMEMB>>>(bq, bk, bv);

    cudaFuncSetAttribute(attn_kernel,
                         cudaFuncAttributeMaxDynamicSharedMemorySize, ATTN_SMEMB);
    attn_kernel<<<dim3(4, NH, NBM), 256, ATTN_SMEMB>>>(out);
}

// round 9
// speedup vs baseline: 1.1688x; 1.1688x over previous
#include <cuda_runtime.h>
#include <cuda_bf16.h>
#include <cstdint>

// Problem constants
#define NBM   64      // B*M = 2*32
#define LSEQ  512
#define CDIM  512
#define NH    8
#define HD    64
#define NROWS (NBM*LSEQ)   // 32768

// Scratch (all tf32-rounded; mma k-dims perm16'd within 16-groups):
__device__ float g_xt[NROWS*CDIM];       // X rows, k perm16
__device__ float g_q[NBM*NH*LSEQ*HD];    // [bm][h][l][d''] d perm16
__device__ float g_k[NBM*NH*LSEQ*HD];    // [bm][h][l][d''] d perm16
__device__ float g_v[NBM*NH*HD*LSEQ];    // [bm][h][d][l''] l perm16
__device__ float g_wt[3*CDIM*CDIM];      // [3][n][k''] k perm16

// perm16: logical v -> 4*(v&3) + ((v>>2)&1) + 2*((v>>3)&1).
// LDS.128 at 16*ksp + 4*t then yields {ksA:t, ksA:t+4, ksB:t, ksB:t+4}.
__device__ __forceinline__ int p16(int v) {
    return 4 * (v & 3) + ((v >> 2) & 1) + 2 * ((v >> 3) & 1);
}

__device__ __forceinline__ unsigned f2tf(float f) {
    unsigned u;
    asm("cvt.rna.tf32.f32 %0, %1;" : "=r"(u) : "f"(f));
    return u;
}
__device__ __forceinline__ float f2tff(float f) { return __uint_as_float(f2tf(f)); }

__device__ __forceinline__ void mma_tf32(float* c, const unsigned* a, const unsigned* b) {
    asm("mma.sync.aligned.m16n8k8.row.col.f32.tf32.tf32.f32 "
        "{%0,%1,%2,%3}, {%4,%5,%6,%7}, {%8,%9}, {%0,%1,%2,%3};"
        : "+f"(c[0]), "+f"(c[1]), "+f"(c[2]), "+f"(c[3])
        : "r"(a[0]), "r"(a[1]), "r"(a[2]), "r"(a[3]),
          "r"(b[0]), "r"(b[1]));
}

__device__ __forceinline__ uint32_t smem_u32(const void* p) {
    uint32_t a;
    asm("{ .reg .u64 t; cvta.to.shared.u64 t, %1; cvt.u32.u64 %0, t; }" : "=r"(a) : "l"(p));
    return a;
}

#define CP16(dst, src) \
    asm volatile("cp.async.cg.shared.global [%0], [%1], 16;" :: "r"(dst), "l"(src) : "memory")
#define CP_COMMIT() asm volatile("cp.async.commit_group;" ::: "memory")
#define CP_WAIT(n)  asm volatile("cp.async.wait_group %0;" :: "n"(n) : "memory")

// ---------------------------------------------------------------------------
// Pre-pass A: g_xt = rna_tf32(x), k perm16'd.
// ---------------------------------------------------------------------------
__global__ __launch_bounds__(256) void xt_kernel(const float* __restrict__ x)
{
    int idx = blockIdx.x * 256 + threadIdx.x;          // float4 index
    float4 v = ((const float4*)x)[idx];
    int fbase = idx * 4;
    int grp   = fbase & ~15;
    int start = (fbase >> 2) & 3;
    float* dst = g_xt + grp + start;
    dst[0]  = f2tff(v.x);
    dst[4]  = f2tff(v.y);
    dst[8]  = f2tff(v.z);
    dst[12] = f2tff(v.w);
}

// ---------------------------------------------------------------------------
// Pre-pass B: Wt[mat][n][k''] = rna_tf32(W[k][n]), k perm16'd.
// ---------------------------------------------------------------------------
__global__ __launch_bounds__(256) void wt_kernel(
    const float* __restrict__ Wq, const float* __restrict__ Wk,
    const float* __restrict__ Wv)
{
    __shared__ float s[32][33];
    const float* W = (blockIdx.z == 0) ? Wq : (blockIdx.z == 1) ? Wk : Wv;
    const int k0 = blockIdx.x * 32, n0 = blockIdx.y * 32;
    const int tid = threadIdx.x;
    {
        int kl = tid >> 3, n4 = tid & 7;
        float4 v = *(const float4*)&W[(size_t)(k0 + kl) * CDIM + n0 + n4 * 4];
        s[kl][n4 * 4 + 0] = f2tff(v.x);
        s[kl][n4 * 4 + 1] = f2tff(v.y);
        s[kl][n4 * 4 + 2] = f2tff(v.z);
        s[kl][n4 * 4 + 3] = f2tff(v.w);
    }
    __syncthreads();
    {
        int nl = tid >> 3, k4 = tid & 7;
        float* rowp = g_wt + ((size_t)(blockIdx.z * CDIM + n0 + nl)) * CDIM;
        #pragma unroll
        for (int j = 0; j < 4; j++) {
            int kk = k0 + k4 * 4 + j;
            int kp = (kk & ~15) | p16(kk & 15);
            rowp[kp] = s[k4 * 4 + j][nl];
        }
    }
}

// ---------------------------------------------------------------------------
// Kernel 1: QKV projection. CTA 128x128, 8 warps (2m x 4n, 64x32 each).
// K=512 in 32 stages of 16, 4-deep cp.async pipeline, 2 CTAs/SM.
// All fragment loads LDS.128 (perm16, packed stride 16 = conflict-free).
// ---------------------------------------------------------------------------
#define QKV_TILEA 2048                   // floats: 128 rows x 16
#define QKV_STAGE (2*QKV_TILEA)          // A + B
#define QKV_SMEMB (4*QKV_STAGE*4)        // 65536 bytes

__global__ __launch_bounds__(256, 2) void qkv_v5(
    const float* __restrict__ bq, const float* __restrict__ bk,
    const float* __restrict__ bv)
{
    extern __shared__ float smem[];
    const uint32_t sbase = smem_u32(smem);

    const int tid  = threadIdx.x;
    const int lane = tid & 31;
    const int warp = tid >> 5;
    const int g    = lane >> 2;
    const int t    = lane & 3;
    const int wm   = (warp >> 2) * 64;
    const int wn   = (warp & 3) * 32;

    const int ntile = blockIdx.x;        // 0..11
    const int mat   = ntile >> 2;
    const int col0  = (ntile & 3) * 128;
    const int r0    = blockIdx.y * 128;
    const float* bias = (mat == 0) ? bq : (mat == 1) ? bk : bv;

    // staging: per stage A 512 chunks + B 512 chunks, 4 CP16/thread
    const int srow = tid >> 2;           // 0..63 (+64 for second)
    const int sc   = tid & 3;
    const float* xsrc = g_xt + (size_t)(r0 + srow) * CDIM + sc * 4;
    const float* wsrc = g_wt + (size_t)(mat * CDIM + col0 + srow) * CDIM + sc * 4;
    const uint32_t sOff = (uint32_t)(srow * 16 + sc * 4) * 4;

    auto stage = [&](int kt, int s) {
        const uint32_t aB = sbase + (uint32_t)s * (QKV_STAGE * 4) + sOff;
        const float* xs = xsrc + kt * 16;
        const float* ws = wsrc + kt * 16;
        CP16(aB,                          xs);
        CP16(aB + 64 * 16 * 4,            xs + (size_t)64 * CDIM);
        CP16(aB + QKV_TILEA * 4,          ws);
        CP16(aB + (QKV_TILEA + 64*16)*4,  ws + (size_t)64 * CDIM);
        CP_COMMIT();
    };

    float acc[4][4][4];
    #pragma unroll
    for (int mi = 0; mi < 4; mi++)
        #pragma unroll
        for (int ni = 0; ni < 4; ni++)
            #pragma unroll
            for (int e = 0; e < 4; e++) acc[mi][ni][e] = 0.f;

    stage(0, 0); stage(1, 1); stage(2, 2);

    for (int kt = 0; kt < 32; kt++) {
        CP_WAIT(2);
        __syncthreads();
        if (kt + 3 < 32) stage(kt + 3, (kt + 3) & 3);
        else             CP_COMMIT();     // keep group count uniform

        const unsigned* As = (const unsigned*)(smem + (kt & 3) * QKV_STAGE);
        const unsigned* Bs = As + QKV_TILEA;

        unsigned aA[4][4], aB2[4][4];
        #pragma unroll
        for (int mi = 0; mi < 4; mi++) {
            int rb = wm + mi * 16 + g;
            uint4 lo = *(const uint4*)&As[rb * 16 + 4 * t];
            uint4 hi = *(const uint4*)&As[(rb + 8) * 16 + 4 * t];
            aA[mi][0] = lo.x; aA[mi][1] = hi.x; aA[mi][2] = lo.y; aA[mi][3] = hi.y;
            aB2[mi][0] = lo.z; aB2[mi][1] = hi.z; aB2[mi][2] = lo.w; aB2[mi][3] = hi.w;
        }
        #pragma unroll
        for (int ni = 0; ni < 4; ni++) {
            uint4 u = *(const uint4*)&Bs[(wn + ni * 8 + g) * 16 + 4 * t];
            unsigned bA[2] = { u.x, u.y }, bB[2] = { u.z, u.w };
            #pragma unroll
            for (int mi = 0; mi < 4; mi++) {
                mma_tf32(acc[mi][ni], aA[mi],  bA);
                mma_tf32(acc[mi][ni], aB2[mi], bB);
            }
        }
    }

    // Epilogue: bias + tf32 round + perm16 scatter
    float* qk = (mat == 0) ? g_q : g_k;
    #pragma unroll
    for (int mi = 0; mi < 4; mi++) {
        #pragma unroll
        for (int ep = 0; ep < 2; ep++) {
            int row = wm + mi * 16 + g + ep * 8;
            int R = r0 + row;
            int bm = R >> 9, l = R & 511;
            int lp = (l & ~15) | p16(l & 15);
            #pragma unroll
            for (int ni = 0; ni < 4; ni++) {
                int c = col0 + wn + ni * 8 + t * 2;
                int h = c >> 6, d = c & 63;
                float v0 = f2tff(acc[mi][ni][2 * ep]     + bias[c]);
                float v1 = f2tff(acc[mi][ni][2 * ep + 1] + bias[c + 1]);
                if (mat < 2) {
                    float* base = qk + (((size_t)(bm * NH + h)) * LSEQ + l) * HD;
                    base[(d & ~15) | p16(d & 15)]             = v0;
                    base[((d + 1) & ~15) | p16((d + 1) & 15)] = v1;
                } else {
                    size_t base = ((size_t)(bm * NH + h)) * HD;
                    g_v[(base + d)     * LSEQ + lp] = v0;
                    g_v[(base + d + 1) * LSEQ + lp] = v1;
                }
            }
        }
    }
}

// ---------------------------------------------------------------------------
// Kernel 2: flash attention. CTA = 256 q-rows (8 warps x 32 rows), j-tiles of
// 64 keys (8 iters). Q frags direct from L2 (LDG). O^T = V^T P^T with P built
// in-register via shuffles (no P smem). smem = K[2]+V[2] tiles only (80 KB).
// ---------------------------------------------------------------------------
#define KST 80
#define KS_OFF(b) ((b) * 64 * KST)
#define VS_OFF(b) (2 * 64 * KST + (b) * 64 * KST)
#define ATTN_FLOATS (4 * 64 * KST)
#define ATTN_SMEMB  (ATTN_FLOATS * 4)    // 81920 bytes

__global__ __launch_bounds__(256, 1) void attn_kernel(float* __restrict__ out)
{
    extern __shared__ float asmem[];
    const uint32_t sbase = smem_u32(asmem);

    const int l0 = blockIdx.x * 256;     // q-tile base (0 or 256)
    const int h  = blockIdx.y;
    const int bm = blockIdx.z;

    const int tid  = threadIdx.x;
    const int lane = tid & 31;
    const int warp = tid >> 5;
    const int g    = lane >> 2;
    const int t    = lane & 3;
    const int wr2  = warp * 32;          // warp's 32 q-rows

    const float* qb = g_q + ((size_t)(bm * NH + h)) * LSEQ * HD;
    const float* kb = g_k + ((size_t)(bm * NH + h)) * LSEQ * HD;
    const float* vb = g_v + ((size_t)(bm * NH + h)) * HD * LSEQ;

    // ---- stage K0 + V0 (j0 = 0) ----
    const int srow = tid >> 2;           // 0..63
    const int sc   = tid & 3;            // 4 chunks of 16B -> 16 floats... (use idx loop)
    #pragma unroll
    for (int i = 0; i < 4; i++) {
        int idx = tid + i * 256;         // 1024 chunks: K tile 64x64 floats
        int row = idx >> 4, c = idx & 15;
        uint32_t dst = sbase + (uint32_t)(KS_OFF(0) + row * KST + c * 4) * 4;
        CP16(dst, kb + (size_t)row * HD + c * 4);
    }
    #pragma unroll
    for (int i = 0; i < 4; i++) {
        int idx = tid + i * 256;
        int row = idx >> 4, c = idx & 15;
        uint32_t dst = sbase + (uint32_t)(VS_OFF(0) + row * KST + c * 4) * 4;
        CP16(dst, vb + (size_t)row * LSEQ + c * 4);
    }
    CP_COMMIT();

    // ---- Q fragments direct from global (L2-resident, perm16'd d) ----
    unsigned qa[2][8][4];
    #pragma unroll
    for (int mi = 0; mi < 2; mi++) {
        #pragma unroll
        for (int ksp = 0; ksp < 4; ksp++) {
            const float* qr = qb + (size_t)(l0 + wr2 + mi * 16 + g) * HD + ksp * 16 + 4 * t;
            uint4 lo = *(const uint4*)qr;
            uint4 hi = *(const uint4*)(qr + 8 * HD);
            qa[mi][2*ksp][0]   = lo.x; qa[mi][2*ksp][1]   = hi.x;
            qa[mi][2*ksp][2]   = lo.y; qa[mi][2*ksp][3]   = hi.y;
            qa[mi][2*ksp+1][0] = lo.z; qa[mi][2*ksp+1][1] = hi.z;
            qa[mi][2*ksp+1][2] = lo.w; qa[mi][2*ksp+1][3] = hi.w;
        }
    }

    // O^T accumulators: oacc[mi_d][nq]: c0=(d=16mi_d+g, q=8nq+2t), c1=(d,q+1),
    // c2=(d+8,q), c3=(d+8,q+1)
    float oacc[4][4][4];
    #pragma unroll
    for (int mi = 0; mi < 4; mi++)
        #pragma unroll
        for (int nq = 0; nq < 4; nq++)
            #pragma unroll
            for (int e = 0; e < 4; e++) oacc[mi][nq][e] = 0.f;

    float mrow[2][2] = { { -3.0e38f, -3.0e38f }, { -3.0e38f, -3.0e38f } };
    float lsum[2][2] = { { 0.f, 0.f }, { 0.f, 0.f } };
    const float kInv = 1.4426950408889634f * 0.125f;  // log2(e)/sqrt(64)
    const int src0 = (lane & ~3) | (t >> 1);
    const int src1 = src0 + 2;

    CP_WAIT(0);
    __syncthreads();

    for (int j = 0; j < 8; j++) {
        const int b = j & 1;
        if (j < 7) {    // prefetch next K/V into other buffer
            const int jn = (j + 1) * 64;
            #pragma unroll
            for (int i = 0; i < 4; i++) {
                int idx = tid + i * 256;
                int row = idx >> 4, c = idx & 15;
                uint32_t dst = sbase + (uint32_t)(KS_OFF(b ^ 1) + row * KST + c * 4) * 4;
                CP16(dst, kb + (size_t)(jn + row) * HD + c * 4);
            }
            #pragma unroll
            for (int i = 0; i < 4; i++) {
                int idx = tid + i * 256;
                int row = idx >> 4, c = idx & 15;
                uint32_t dst = sbase + (uint32_t)(VS_OFF(b ^ 1) + row * KST + c * 4) * 4;
                CP16(dst, vb + (size_t)row * LSEQ + jn + c * 4);
            }
            CP_COMMIT();
        }

        const unsigned* Ks = (const unsigned*)(asmem + KS_OFF(b));
        const unsigned* Vs = (const unsigned*)(asmem + VS_OFF(b));

        // ---- S = Q K^T : sacc[mi][ni]: rows {wr2+16mi+g,+8}, keys 8ni+2t(+1)
        float sacc[2][8][4];
        #pragma unroll
        for (int mi = 0; mi < 2; mi++)
            #pragma unroll
            for (int ni = 0; ni < 8; ni++)
                #pragma unroll
                for (int e = 0; e < 4; e++) sacc[mi][ni][e] = 0.f;

        #pragma unroll
        for (int ksp = 0; ksp < 4; ksp++) {
            #pragma unroll
            for (int ni = 0; ni < 8; ni++) {
                uint4 u = *(const uint4*)&Ks[(ni * 8 + g) * KST + ksp * 16 + 4 * t];
                unsigned bA[2] = { u.x, u.y }, bB[2] = { u.z, u.w };
                #pragma unroll
                for (int mi = 0; mi < 2; mi++) {
                    mma_tf32(sacc[mi][ni], qa[mi][2*ksp],   bA);
                    mma_tf32(sacc[mi][ni], qa[mi][2*ksp+1], bB);
                }
            }
        }

        #pragma unroll
        for (int mi = 0; mi < 2; mi++)
            #pragma unroll
            for (int ni = 0; ni < 8; ni++)
                #pragma unroll
                for (int e = 0; e < 4; e++) sacc[mi][ni][e] *= kInv;

        // ---- online softmax (base 2); sacc -> rounded P ----
        float alpha[2][2];
        #pragma unroll
        for (int mi = 0; mi < 2; mi++) {
            #pragma unroll
            for (int e = 0; e < 2; e++) {
                float mt = -3.0e38f;
                #pragma unroll
                for (int ni = 0; ni < 8; ni++) {
                    mt = fmaxf(mt, sacc[mi][ni][2 * e]);
                    mt = fmaxf(mt, sacc[mi][ni][2 * e + 1]);
                }
                mt = fmaxf(mt, __shfl_xor_sync(0xffffffffu, mt, 1));
                mt = fmaxf(mt, __shfl_xor_sync(0xffffffffu, mt, 2));
                float mnew = fmaxf(mrow[mi][e], mt);
                alpha[mi][e] = exp2f(mrow[mi][e] - mnew);
                mrow[mi][e]  = mnew;
                float rs = 0.f;
                #pragma unroll
                for (int ni = 0; ni < 8; ni++) {
                    float p0 = exp2f(sacc[mi][ni][2 * e]     - mnew);
                    float p1 = exp2f(sacc[mi][ni][2 * e + 1] - mnew);
                    rs += p0 + p1;
                    sacc[mi][ni][2 * e]     = f2tff(p0);
                    sacc[mi][ni][2 * e + 1] = f2tff(p1);
                }
                rs += __shfl_xor_sync(0xffffffffu, rs, 1);
                rs += __shfl_xor_sync(0xffffffffu, rs, 2);
                lsum[mi][e] = lsum[mi][e] * alpha[mi][e] + rs;
            }
        }

        // ---- rescale O^T by output-row alphas (rows 8nq+2t, +1) ----
        #pragma unroll
        for (int nq = 0; nq < 4; nq++) {
            float av = alpha[nq >> 1][nq & 1];
            float a0 = __shfl_sync(0xffffffffu, av, 8 * t);
            float a1 = __shfl_sync(0xffffffffu, av, 8 * t + 4);
            #pragma unroll
            for (int mi = 0; mi < 4; mi++) {
                oacc[mi][nq][0] *= a0; oacc[mi][nq][2] *= a0;
                oacc[mi][nq][1] *= a1; oacc[mi][nq][3] *= a1;
            }
        }

        // ---- O^T += V^T P^T (A = V^T from smem, B = P^T via shuffles) ----
        #pragma unroll
        for (int ksp = 0; ksp < 4; ksp++) {
            unsigned aA[4][4], aB[4][4];
            #pragma unroll
            for (int mi = 0; mi < 4; mi++) {
                uint4 lo = *(const uint4*)&Vs[(mi * 16 + g) * KST + ksp * 16 + 4 * t];
                uint4 hi = *(const uint4*)&Vs[(mi * 16 + g + 8) * KST + ksp * 16 + 4 * t];
                aA[mi][0] = lo.x; aA[mi][1] = hi.x; aA[mi][2] = lo.y; aA[mi][3] = hi.y;
                aB[mi][0] = lo.z; aB[mi][1] = hi.z; aB[mi][2] = lo.w; aB[mi][3] = hi.w;
            }
            #pragma unroll
            for (int h2 = 0; h2 < 2; h2++) {
                const int ks = 2 * ksp + h2;
                #pragma unroll
                for (int nq = 0; nq < 4; nq++) {
                    float v00 = __shfl_sync(0xffffffffu, sacc[nq >> 1][ks][2 * (nq & 1)],     src0);
                    float v01 = __shfl_sync(0xffffffffu, sacc[nq >> 1][ks][2 * (nq & 1) + 1], src0);
                    float v10 = __shfl_sync(0xffffffffu, sacc[nq >> 1][ks][2 * (nq & 1)],     src1);
                    float v11 = __shfl_sync(0xffffffffu, sacc[nq >> 1][ks][2 * (nq & 1) + 1], src1);
                    unsigned bf[2];
                    bf[0] = __float_as_uint((t & 1) ? v01 : v00);
                    bf[1] = __float_as_uint((t & 1) ? v11 : v10);
                    #pragma unroll
                    for (int mi = 0; mi < 4; mi++)
                        mma_tf32(oacc[mi][nq], h2 ? aB[mi] : aA[mi], bf);
                }
            }
        }

        if (j < 7) CP_WAIT(0);
        __syncthreads();
    }

    // ---- epilogue: per-row 1/lsum via shuffle, transposed STG ----
    #pragma unroll
    for (int nq = 0; nq < 4; nq++) {
        float lv = lsum[nq >> 1][nq & 1];
        float L0 = __shfl_sync(0xffffffffu, lv, 8 * t);
        float L1 = __shfl_sync(0xffffffffu, lv, 8 * t + 4);
        float inv0 = 1.f / L0, inv1 = 1.f / L1;
        int q0 = l0 + wr2 + 8 * nq + 2 * t;
        float* o0 = out + ((size_t)bm * LSEQ + q0) * CDIM + h * HD;
        float* o1 = o0 + CDIM;
        #pragma unroll
        for (int mi = 0; mi < 4; mi++) {
            o0[mi * 16 + g]     = oacc[mi][nq][0] * inv0;
            o1[mi * 16 + g]     = oacc[mi][nq][1] * inv1;
            o0[mi * 16 + g + 8] = oacc[mi][nq][2] * inv0;
            o1[mi * 16 + g + 8] = oacc[mi][nq][3] * inv1;
        }
    }
}

extern "C" void kernel_launch(void* const* d_in, const int* in_sizes, int n_in,
                              void* d_out, int out_size)
{
    const float* x  = (const float*)d_in[0];
    const float* Wq = (const float*)d_in[1];
    const float* bq = (const float*)d_in[2];
    const float* Wk = (const float*)d_in[3];
    const float* bk = (const float*)d_in[4];
    const float* Wv = (const float*)d_in[5];
    const float* bv = (const float*)d_in[6];
    float* out = (float*)d_out;

    xt_kernel<<<NROWS * CDIM / 4 / 256, 256>>>(x);
    wt_kernel<<<dim3(16, 16, 3), 256>>>(Wq, Wk, Wv);

    cudaFuncSetAttribute(qkv_v5,
                         cudaFuncAttributeMaxDynamicSharedMemorySize, QKV_SMEMB);
    qkv_v5<<<dim3(12, 256), 256, QKV_SMEMB>>>(bq, bk, bv);

    cudaFuncSetAttribute(attn_kernel,
                         cudaFuncAttributeMaxDynamicSharedMemorySize, ATTN_SMEMB);
    attn_kernel<<<dim3(2, NH, NBM), 256, ATTN_SMEMB>>>(out);
}